// round 1
// baseline (speedup 1.0000x reference)
#include <cuda_runtime.h>
#include <cuda_bf16.h>
#include <math.h>
#include <stdint.h>

// Problem constants
#define BB    8
#define NQ    900
#define DD    256
#define HH    8
#define HD    32
#define PP    4
#define BEV   200
#define FFN   512
#define MROWS (BB * NQ)          // 7200

// ---------------- scratch (allocation-free: __device__ globals) -------------
__device__ float g_qin  [MROWS * DD];
__device__ float g_qkv  [MROWS * 3 * DD];
__device__ float g_attn [MROWS * DD];
__device__ float g_q1   [MROWS * DD];
__device__ float g_q2   [MROWS * DD];
__device__ float g_offs [MROWS * HH * PP * 2];
__device__ float g_wts  [MROWS * HH * PP];
__device__ float g_fused[MROWS * DD];
__device__ float g_qq2  [MROWS * DD];
__device__ float g_q3   [MROWS * DD];
__device__ float g_mid  [MROWS * FFN];

// ---------------- block reduce helper ---------------------------------------
__inline__ __device__ float block_reduce_sum_256(float v, float* sh) {
    int lane = threadIdx.x & 31, w = threadIdx.x >> 5;
    #pragma unroll
    for (int o = 16; o; o >>= 1) v += __shfl_xor_sync(0xffffffffu, v, o);
    if (lane == 0) sh[w] = v;
    __syncthreads();
    if (w == 0) {
        float t = (lane < 8) ? sh[lane] : 0.f;
        #pragma unroll
        for (int o = 4; o; o >>= 1) t += __shfl_xor_sync(0xffffffffu, t, o);
        if (lane == 0) sh[0] = t;
    }
    __syncthreads();
    float r = sh[0];
    __syncthreads();   // allow caller to reuse sh
    return r;
}

// ---------------- fused add + LayerNorm (rows of 256) -----------------------
__global__ void add_ln_kernel(const float* __restrict__ a, const float* __restrict__ b,
                              const float* __restrict__ s, const float* __restrict__ bias,
                              float* __restrict__ out) {
    __shared__ float sh[8];
    int row = blockIdx.x, t = threadIdx.x;
    size_t idx = (size_t)row * DD + t;
    float x = a[idx] + (b ? b[idx] : 0.f);
    float mean = block_reduce_sum_256(x, sh) * (1.f / DD);
    float xc = x - mean;
    float var = block_reduce_sum_256(xc * xc, sh) * (1.f / DD);
    out[idx] = xc * rsqrtf(var + 1e-5f) * s[t] + bias[t];
}

// ---------------- generic NT GEMM: C[M,N] = A[M,K] * B[N,K]^T + epi ---------
// 64x64 tile, BK=16, 256 threads, 4x4 per thread
__global__ void gemm_nt(const float* __restrict__ A, const float* __restrict__ B,
                        const float* __restrict__ bias, const float* __restrict__ resid,
                        float* __restrict__ C, int M, int N, int K, int relu) {
    __shared__ float As[16][68];
    __shared__ float Bs[16][68];
    int tid = threadIdx.x;
    int tx = tid & 15, ty = tid >> 4;
    int bm = blockIdx.y * 64, bn = blockIdx.x * 64;
    int lm = tid >> 2;            // 0..63 row within tile
    int kq = (tid & 3) * 4;       // 0,4,8,12
    float acc[4][4] = {};
    for (int k0 = 0; k0 < K; k0 += 16) {
        int gm = bm + lm;
        float4 va = make_float4(0.f, 0.f, 0.f, 0.f);
        if (gm < M) va = *(const float4*)(A + (size_t)gm * K + k0 + kq);
        As[kq + 0][lm] = va.x; As[kq + 1][lm] = va.y;
        As[kq + 2][lm] = va.z; As[kq + 3][lm] = va.w;
        int gn = bn + lm;
        float4 vb = make_float4(0.f, 0.f, 0.f, 0.f);
        if (gn < N) vb = *(const float4*)(B + (size_t)gn * K + k0 + kq);
        Bs[kq + 0][lm] = vb.x; Bs[kq + 1][lm] = vb.y;
        Bs[kq + 2][lm] = vb.z; Bs[kq + 3][lm] = vb.w;
        __syncthreads();
        #pragma unroll
        for (int k = 0; k < 16; k++) {
            float4 a4 = *(const float4*)&As[k][ty * 4];
            float4 b4 = *(const float4*)&Bs[k][tx * 4];
            float af[4] = {a4.x, a4.y, a4.z, a4.w};
            float bf[4] = {b4.x, b4.y, b4.z, b4.w};
            #pragma unroll
            for (int i = 0; i < 4; i++)
                #pragma unroll
                for (int j = 0; j < 4; j++)
                    acc[i][j] += af[i] * bf[j];
        }
        __syncthreads();
    }
    #pragma unroll
    for (int i = 0; i < 4; i++) {
        int r = bm + ty * 4 + i;
        if (r >= M) continue;
        #pragma unroll
        for (int j = 0; j < 4; j++) {
            int c = bn + tx * 4 + j;
            if (c >= N) continue;
            float v = acc[i][j];
            if (bias) v += bias[c];
            if (relu) v = fmaxf(v, 0.f);
            if (resid) v += resid[(size_t)r * N + c];
            C[(size_t)r * N + c] = v;
        }
    }
}

// ---------------- fused self-attention (flash-style) ------------------------
// grid: (29 qtiles, H, B); 256 threads. 32-query x 64-key tiles, HD=32.
__global__ void attn_kernel(const float* __restrict__ qkv, float* __restrict__ out) {
    const int b = blockIdx.z, h = blockIdx.y, qt = blockIdx.x;
    __shared__ float Qs[32][33];
    __shared__ float Ks[64][33];
    __shared__ float Vs[64][33];
    __shared__ float Ps[32][64];
    int tid = threadIdx.x;
    for (int idx = tid; idx < 32 * 32; idx += 256) {
        int i = idx >> 5, d = idx & 31;
        int q = qt * 32 + i;
        Qs[i][d] = (q < NQ) ? qkv[((size_t)(b * NQ + q)) * 768 + h * HD + d] : 0.f;
    }
    int qrow = tid >> 3, sub = tid & 7;
    float o0 = 0.f, o1 = 0.f, o2 = 0.f, o3 = 0.f;
    float m_i = -INFINITY, l_i = 0.f;
    const float scale = 0.17677669529663687f;   // 1/sqrt(32)
    const unsigned full = 0xffffffffu;
    for (int jt = 0; jt < 15; jt++) {
        __syncthreads();
        for (int idx = tid; idx < 64 * 32; idx += 256) {
            int j = idx >> 5, d = idx & 31;
            int kk = jt * 64 + j;
            float kv = 0.f, vv = 0.f;
            if (kk < NQ) {
                size_t base = ((size_t)(b * NQ + kk)) * 768 + h * HD + d;
                kv = qkv[base + 256];
                vv = qkv[base + 512];
            }
            Ks[j][d] = kv; Vs[j][d] = vv;
        }
        __syncthreads();
        float sv[8];
        #pragma unroll
        for (int e = 0; e < 8; e++) {
            int j = sub * 8 + e;
            float acc = 0.f;
            #pragma unroll
            for (int d = 0; d < 32; d++) acc += Qs[qrow][d] * Ks[j][d];
            int kk = jt * 64 + j;
            sv[e] = (kk < NQ) ? acc * scale : -INFINITY;
        }
        float tmax = sv[0];
        #pragma unroll
        for (int e = 1; e < 8; e++) tmax = fmaxf(tmax, sv[e]);
        #pragma unroll
        for (int o = 1; o < 8; o <<= 1)
            tmax = fmaxf(tmax, __shfl_xor_sync(full, tmax, o));
        float newm = fmaxf(m_i, tmax);
        float fac = expf(m_i - newm);
        float tsum = 0.f;
        #pragma unroll
        for (int e = 0; e < 8; e++) {
            float p = expf(sv[e] - newm);
            Ps[qrow][sub * 8 + e] = p;
            tsum += p;
        }
        #pragma unroll
        for (int o = 1; o < 8; o <<= 1)
            tsum += __shfl_xor_sync(full, tsum, o);
        l_i = l_i * fac + tsum;
        m_i = newm;
        o0 *= fac; o1 *= fac; o2 *= fac; o3 *= fac;
        __syncwarp();
        #pragma unroll
        for (int j = 0; j < 64; j++) {
            float p = Ps[qrow][j];
            o0 += p * Vs[j][sub];
            o1 += p * Vs[j][sub + 8];
            o2 += p * Vs[j][sub + 16];
            o3 += p * Vs[j][sub + 24];
        }
    }
    int q = qt * 32 + qrow;
    if (q < NQ) {
        float inv = 1.f / l_i;
        size_t base = ((size_t)(b * NQ + q)) * DD + h * HD + sub;
        out[base]      = o0 * inv;
        out[base + 8]  = o1 * inv;
        out[base + 16] = o2 * inv;
        out[base + 24] = o3 * inv;
    }
}

// ---------------- deformable sampling: warp = (head), block = (b,q) ---------
__global__ void sample_kernel(const float* __restrict__ mem, const float* __restrict__ ref,
                              const float* __restrict__ offs, const float* __restrict__ wts,
                              float* __restrict__ fused) {
    int row = blockIdx.x;           // b*NQ + q
    int b = row / NQ;
    int h = threadIdx.x >> 5;
    int lane = threadIdx.x & 31;
    const unsigned full = 0xffffffffu;
    float rx = ref[row * 2], ry = ref[row * 2 + 1];
    float gx = 0.f, gy = 0.f, wl = 0.f;
    if (lane < PP) {
        float ox = offs[(size_t)row * (HH * PP * 2) + h * (PP * 2) + lane * 2];
        float oy = offs[(size_t)row * (HH * PP * 2) + h * (PP * 2) + lane * 2 + 1];
        gx = (rx + tanhf(ox) * 0.2f) * (float)BEV - 0.5f;
        gy = (ry + tanhf(oy) * 0.2f) * (float)BEV - 0.5f;
        wl = wts[(size_t)row * (HH * PP) + h * PP + lane];
    }
    // softmax over 4 lanes (lanes >=4 compute garbage, unused)
    float m = wl;
    m = fmaxf(m, __shfl_xor_sync(full, m, 1));
    m = fmaxf(m, __shfl_xor_sync(full, m, 2));
    float e = __expf(wl - m);
    float ssum = e;
    ssum += __shfl_xor_sync(full, ssum, 1);
    ssum += __shfl_xor_sync(full, ssum, 2);
    float w = e / ssum;
    const float* mb = mem + (size_t)b * (BEV * BEV) * DD + h * HD + lane;
    float acc = 0.f;
    #pragma unroll
    for (int p = 0; p < PP; p++) {
        float px = __shfl_sync(full, gx, p);
        float py = __shfl_sync(full, gy, p);
        float pw = __shfl_sync(full, w, p);
        float x0f = floorf(px), y0f = floorf(py);
        float wx1 = px - x0f, wy1 = py - y0f;
        float wx0 = 1.f - wx1, wy0 = 1.f - wy1;
        int x0 = (int)x0f, y0 = (int)y0f;
        bool xv0 = (x0 >= 0) && (x0 < BEV);
        bool xv1 = (x0 + 1 >= 0) && (x0 + 1 < BEV);
        bool yv0 = (y0 >= 0) && (y0 < BEV);
        bool yv1 = (y0 + 1 >= 0) && (y0 + 1 < BEV);
        float v = 0.f;
        if (yv0) {
            if (xv0) v += wx0 * wy0 * mb[(size_t)(y0 * BEV + x0) * DD];
            if (xv1) v += wx1 * wy0 * mb[(size_t)(y0 * BEV + x0 + 1) * DD];
        }
        if (yv1) {
            if (xv0) v += wx0 * wy1 * mb[(size_t)((y0 + 1) * BEV + x0) * DD];
            if (xv1) v += wx1 * wy1 * mb[(size_t)((y0 + 1) * BEV + x0 + 1) * DD];
        }
        acc += pw * v;
    }
    fused[(size_t)row * DD + h * HD + lane] = acc;
}

// ---------------- host launcher ---------------------------------------------
extern "C" void kernel_launch(void* const* d_in, const int* in_sizes, int n_in,
                              void* d_out, int out_size) {
    const float* query = (const float*)d_in[0];
    const float* memory = (const float*)d_in[1];
    const float* refp  = (const float*)d_in[2];
    const float* qpos  = (const float*)d_in[3];
    const float* in_w  = (const float*)d_in[4];
    const float* in_b  = (const float*)d_in[5];
    const float* out_w = (const float*)d_in[6];
    const float* out_b = (const float*)d_in[7];
    const float* off_w = (const float*)d_in[8];
    const float* off_b = (const float*)d_in[9];
    const float* wt_w  = (const float*)d_in[10];
    const float* wt_b  = (const float*)d_in[11];
    const float* co_w  = (const float*)d_in[12];
    const float* co_b  = (const float*)d_in[13];
    const float* f_w1  = (const float*)d_in[14];
    const float* f_b1  = (const float*)d_in[15];
    const float* f_w2  = (const float*)d_in[16];
    const float* f_b2  = (const float*)d_in[17];
    const float* n1s   = (const float*)d_in[18];
    const float* n1b   = (const float*)d_in[19];
    const float* n2s   = (const float*)d_in[20];
    const float* n2b   = (const float*)d_in[21];
    const float* n3s   = (const float*)d_in[22];
    const float* n3b   = (const float*)d_in[23];

    float *qin, *qkv, *attn, *q1, *q2, *offs, *wts, *fused, *qq2, *q3, *mid;
    cudaGetSymbolAddress((void**)&qin,   g_qin);
    cudaGetSymbolAddress((void**)&qkv,   g_qkv);
    cudaGetSymbolAddress((void**)&attn,  g_attn);
    cudaGetSymbolAddress((void**)&q1,    g_q1);
    cudaGetSymbolAddress((void**)&q2,    g_q2);
    cudaGetSymbolAddress((void**)&offs,  g_offs);
    cudaGetSymbolAddress((void**)&wts,   g_wts);
    cudaGetSymbolAddress((void**)&fused, g_fused);
    cudaGetSymbolAddress((void**)&qq2,   g_qq2);
    cudaGetSymbolAddress((void**)&q3,    g_q3);
    cudaGetSymbolAddress((void**)&mid,   g_mid);

    const int M = MROWS;
    const int MT = (M + 63) / 64;   // 113

    // 1. q_in = LN(query + query_pos)
    add_ln_kernel<<<M, 256>>>(query, qpos, n1s, n1b, qin);
    // 2. qkv = q_in @ in_w^T + in_b
    gemm_nt<<<dim3(12, MT), 256>>>(qin, in_w, in_b, nullptr, qkv, M, 768, 256, 0);
    // 3. self-attention
    attn_kernel<<<dim3(29, HH, BB), 256>>>(qkv, attn);
    // 4. q1 = attn @ out_w^T + out_b + query
    gemm_nt<<<dim3(4, MT), 256>>>(attn, out_w, out_b, query, q1, M, 256, 256, 0);
    // 5. q2 = LN(q1 + query_pos)
    add_ln_kernel<<<M, 256>>>(q1, qpos, n2s, n2b, q2);
    // 6/7. offset + weight heads
    gemm_nt<<<dim3(1, MT), 256>>>(q2, off_w, off_b, nullptr, offs, M, 64, 256, 0);
    gemm_nt<<<dim3(1, MT), 256>>>(q2, wt_w, wt_b, nullptr, wts, M, 32, 256, 0);
    // 8. deformable BEV sampling -> fused
    sample_kernel<<<M, 256>>>(memory, refp, offs, wts, fused);
    // 9. qq2 = fused @ co_w^T + co_b + q1
    gemm_nt<<<dim3(4, MT), 256>>>(fused, co_w, co_b, q1, qq2, M, 256, 256, 0);
    // 10. q3 = LN(qq2)
    add_ln_kernel<<<M, 256>>>(qq2, nullptr, n3s, n3b, q3);
    // 11. mid = relu(q3 @ f_w1^T + f_b1)
    gemm_nt<<<dim3(8, MT), 256>>>(q3, f_w1, f_b1, nullptr, mid, M, 512, 256, 1);
    // 12. out = mid @ f_w2^T + f_b2 + qq2
    gemm_nt<<<dim3(4, MT), 256>>>(mid, f_w2, f_b2, qq2, (float*)d_out, M, 256, 512, 0);
    (void)in_sizes; (void)n_in; (void)out_size;
}

// round 2
// speedup vs baseline: 1.5319x; 1.5319x over previous
#include <cuda_runtime.h>
#include <cuda_bf16.h>
#include <math.h>
#include <stdint.h>

// Problem constants
#define BB    8
#define NQ    900
#define DD    256
#define HH    8
#define HD    32
#define PP    4
#define BEV   200
#define FFN   512
#define MROWS (BB * NQ)          // 7200

// ---------------- scratch (allocation-free: __device__ globals) -------------
__device__ float g_qin  [MROWS * DD];
__device__ float g_qkv  [MROWS * 3 * DD];
__device__ float g_attn [MROWS * DD];
__device__ float g_q1   [MROWS * DD];
__device__ float g_q2   [MROWS * DD];
__device__ float g_offs [MROWS * HH * PP * 2];
__device__ float g_wts  [MROWS * HH * PP];
__device__ float g_fused[MROWS * DD];
__device__ float g_qq2  [MROWS * DD];
__device__ float g_q3   [MROWS * DD];
__device__ float g_mid  [MROWS * FFN];

// ---------------- block reduce helper ---------------------------------------
__inline__ __device__ float block_reduce_sum_256(float v, float* sh) {
    int lane = threadIdx.x & 31, w = threadIdx.x >> 5;
    #pragma unroll
    for (int o = 16; o; o >>= 1) v += __shfl_xor_sync(0xffffffffu, v, o);
    if (lane == 0) sh[w] = v;
    __syncthreads();
    if (w == 0) {
        float t = (lane < 8) ? sh[lane] : 0.f;
        #pragma unroll
        for (int o = 4; o; o >>= 1) t += __shfl_xor_sync(0xffffffffu, t, o);
        if (lane == 0) sh[0] = t;
    }
    __syncthreads();
    float r = sh[0];
    __syncthreads();
    return r;
}

// ---------------- fused add + LayerNorm (rows of 256) -----------------------
__global__ void add_ln_kernel(const float* __restrict__ a, const float* __restrict__ b,
                              const float* __restrict__ s, const float* __restrict__ bias,
                              float* __restrict__ out) {
    __shared__ float sh[8];
    int row = blockIdx.x, t = threadIdx.x;
    size_t idx = (size_t)row * DD + t;
    float x = a[idx] + (b ? b[idx] : 0.f);
    float mean = block_reduce_sum_256(x, sh) * (1.f / DD);
    float xc = x - mean;
    float var = block_reduce_sum_256(xc * xc, sh) * (1.f / DD);
    out[idx] = xc * rsqrtf(var + 1e-5f) * s[t] + bias[t];
}

// ---------------- big NT GEMM: 128x128 tile, 8x8 micro, BK=8 ----------------
// C[M,N] = A[M,K] * B[N,K]^T (+bias)(+relu)(+resid). Requires N%128==0, K%8==0.
__global__ __launch_bounds__(256, 2)
void gemm128(const float* __restrict__ A, const float* __restrict__ B,
             const float* __restrict__ bias, const float* __restrict__ resid,
             float* __restrict__ C, int M, int N, int K, int relu) {
    __shared__ float As[8][132];
    __shared__ float Bs[8][132];
    int tid = threadIdx.x;
    int bm = blockIdx.y * 128, bn = blockIdx.x * 128;
    int lr = tid >> 1;            // 0..127
    int lk = (tid & 1) * 4;       // 0 or 4
    int ty = tid >> 4, tx = tid & 15;
    float acc[8][8] = {};
    for (int k0 = 0; k0 < K; k0 += 8) {
        int gm = bm + lr;
        float4 va = make_float4(0.f, 0.f, 0.f, 0.f);
        if (gm < M) va = *(const float4*)(A + (size_t)gm * K + k0 + lk);
        As[lk + 0][lr] = va.x; As[lk + 1][lr] = va.y;
        As[lk + 2][lr] = va.z; As[lk + 3][lr] = va.w;
        int gn = bn + lr;   // always < N (N multiple of 128)
        float4 vb = *(const float4*)(B + (size_t)gn * K + k0 + lk);
        Bs[lk + 0][lr] = vb.x; Bs[lk + 1][lr] = vb.y;
        Bs[lk + 2][lr] = vb.z; Bs[lk + 3][lr] = vb.w;
        __syncthreads();
        #pragma unroll
        for (int k = 0; k < 8; k++) {
            float a[8], b[8];
            *(float4*)(a)     = *(const float4*)&As[k][ty * 8];
            *(float4*)(a + 4) = *(const float4*)&As[k][ty * 8 + 4];
            *(float4*)(b)     = *(const float4*)&Bs[k][tx * 8];
            *(float4*)(b + 4) = *(const float4*)&Bs[k][tx * 8 + 4];
            #pragma unroll
            for (int i = 0; i < 8; i++)
                #pragma unroll
                for (int j = 0; j < 8; j++)
                    acc[i][j] += a[i] * b[j];
        }
        __syncthreads();
    }
    int c0 = bn + tx * 8;
    float bv[8];
    #pragma unroll
    for (int j = 0; j < 8; j++) bv[j] = bias ? bias[c0 + j] : 0.f;
    #pragma unroll
    for (int i = 0; i < 8; i++) {
        int r = bm + ty * 8 + i;
        if (r >= M) continue;
        float o[8];
        #pragma unroll
        for (int j = 0; j < 8; j++) {
            float v = acc[i][j] + bv[j];
            if (relu) v = fmaxf(v, 0.f);
            o[j] = v;
        }
        if (resid) {
            float4 r0 = *(const float4*)(resid + (size_t)r * N + c0);
            float4 r1 = *(const float4*)(resid + (size_t)r * N + c0 + 4);
            o[0] += r0.x; o[1] += r0.y; o[2] += r0.z; o[3] += r0.w;
            o[4] += r1.x; o[5] += r1.y; o[6] += r1.z; o[7] += r1.w;
        }
        *(float4*)(C + (size_t)r * N + c0)     = make_float4(o[0], o[1], o[2], o[3]);
        *(float4*)(C + (size_t)r * N + c0 + 4) = make_float4(o[4], o[5], o[6], o[7]);
    }
}

// ---------------- small NT GEMM (N=64/32 heads): 64x64 tile, 4x4 micro ------
__global__ void gemm_nt(const float* __restrict__ A, const float* __restrict__ B,
                        const float* __restrict__ bias, const float* __restrict__ resid,
                        float* __restrict__ C, int M, int N, int K, int relu) {
    __shared__ float As[16][68];
    __shared__ float Bs[16][68];
    int tid = threadIdx.x;
    int tx = tid & 15, ty = tid >> 4;
    int bm = blockIdx.y * 64, bn = blockIdx.x * 64;
    int lm = tid >> 2;
    int kq = (tid & 3) * 4;
    float acc[4][4] = {};
    for (int k0 = 0; k0 < K; k0 += 16) {
        int gm = bm + lm;
        float4 va = make_float4(0.f, 0.f, 0.f, 0.f);
        if (gm < M) va = *(const float4*)(A + (size_t)gm * K + k0 + kq);
        As[kq + 0][lm] = va.x; As[kq + 1][lm] = va.y;
        As[kq + 2][lm] = va.z; As[kq + 3][lm] = va.w;
        int gn = bn + lm;
        float4 vb = make_float4(0.f, 0.f, 0.f, 0.f);
        if (gn < N) vb = *(const float4*)(B + (size_t)gn * K + k0 + kq);
        Bs[kq + 0][lm] = vb.x; Bs[kq + 1][lm] = vb.y;
        Bs[kq + 2][lm] = vb.z; Bs[kq + 3][lm] = vb.w;
        __syncthreads();
        #pragma unroll
        for (int k = 0; k < 16; k++) {
            float4 a4 = *(const float4*)&As[k][ty * 4];
            float4 b4 = *(const float4*)&Bs[k][tx * 4];
            float af[4] = {a4.x, a4.y, a4.z, a4.w};
            float bf[4] = {b4.x, b4.y, b4.z, b4.w};
            #pragma unroll
            for (int i = 0; i < 4; i++)
                #pragma unroll
                for (int j = 0; j < 4; j++)
                    acc[i][j] += af[i] * bf[j];
        }
        __syncthreads();
    }
    #pragma unroll
    for (int i = 0; i < 4; i++) {
        int r = bm + ty * 4 + i;
        if (r >= M) continue;
        #pragma unroll
        for (int j = 0; j < 4; j++) {
            int c = bn + tx * 4 + j;
            if (c >= N) continue;
            float v = acc[i][j];
            if (bias) v += bias[c];
            if (relu) v = fmaxf(v, 0.f);
            if (resid) v += resid[(size_t)r * N + c];
            C[(size_t)r * N + c] = v;
        }
    }
}

// ---------------- fused self-attention v2 ------------------------------------
// 128-query x 64-key tiles, HD=32, 128 threads.
// Smem (dynamic): Qs[32][132] Ks[32][68] Vs[64][36] Ps[64][132]  (~68.6 KB)
#define QT 128
#define KT 64
#define QS(d,q) Qs[(d) * 132 + (q)]
#define KS(d,k) Ks[(d) * 68 + (k)]
#define VS(k,d) Vs[(k) * 36 + (d)]
#define PS(k,q) Ps[(k) * 132 + (q)]

__global__ __launch_bounds__(128)
void attn2_kernel(const float* __restrict__ qkv, float* __restrict__ out) {
    extern __shared__ float sm[];
    float* Qs = sm;                  // 4224 floats
    float* Ks = Qs + 32 * 132;       // 2176
    float* Vs = Ks + 32 * 68;        // 2304
    float* Ps = Vs + 64 * 36;        // 8448

    const int b = blockIdx.z, h = blockIdx.y, qt = blockIdx.x;
    const int tid = threadIdx.x;
    const int ty = tid >> 3;         // 0..15  (q-group of 8; also PV q-group)
    const int tx = tid & 7;          // 0..7   (k-group of 8; also PV d-group of 4)
    const float scale = 0.17677669529663687f;  // 1/sqrt(32)
    const unsigned full = 0xffffffffu;

    // ---- load Q tile (prescaled), transposed Qs[d][q] ----
    {
        int q = qt * QT + tid;
        if (q < NQ) {
            const float* src = qkv + ((size_t)(b * NQ + q)) * 768 + h * HD;
            #pragma unroll
            for (int d4 = 0; d4 < 32; d4 += 4) {
                float4 v = *(const float4*)(src + d4);
                QS(d4 + 0, tid) = v.x * scale; QS(d4 + 1, tid) = v.y * scale;
                QS(d4 + 2, tid) = v.z * scale; QS(d4 + 3, tid) = v.w * scale;
            }
        } else {
            #pragma unroll
            for (int d = 0; d < 32; d++) QS(d, tid) = 0.f;
        }
    }

    float m_r[8], l_r[8], fac[8];
    float O[8][4];
    #pragma unroll
    for (int i = 0; i < 8; i++) {
        m_r[i] = -INFINITY; l_r[i] = 0.f;
        #pragma unroll
        for (int d = 0; d < 4; d++) O[i][d] = 0.f;
    }

    const int NKT = (NQ + KT - 1) / KT;   // 15
    for (int jt = 0; jt < NKT; jt++) {
        __syncthreads();   // prev PV done; safe to overwrite K/V
        // ---- load K (transposed) and V tiles ----
        if (tid < 64) {
            int kk = jt * KT + tid;
            if (kk < NQ) {
                const float* src = qkv + ((size_t)(b * NQ + kk)) * 768 + 256 + h * HD;
                #pragma unroll
                for (int d4 = 0; d4 < 32; d4 += 4) {
                    float4 v = *(const float4*)(src + d4);
                    KS(d4 + 0, tid) = v.x; KS(d4 + 1, tid) = v.y;
                    KS(d4 + 2, tid) = v.z; KS(d4 + 3, tid) = v.w;
                }
            } else {
                #pragma unroll
                for (int d = 0; d < 32; d++) KS(d, tid) = 0.f;
            }
        } else {
            int kk = jt * KT + tid - 64;
            float* dst = &VS(tid - 64, 0);
            if (kk < NQ) {
                const float* src = qkv + ((size_t)(b * NQ + kk)) * 768 + 512 + h * HD;
                #pragma unroll
                for (int d4 = 0; d4 < 32; d4 += 4)
                    *(float4*)(dst + d4) = *(const float4*)(src + d4);
            } else {
                #pragma unroll
                for (int d = 0; d < 32; d++) dst[d] = 0.f;
            }
        }
        __syncthreads();

        // ---- QK: 8x8 microtile ----
        float s[8][8];
        #pragma unroll
        for (int i = 0; i < 8; i++)
            #pragma unroll
            for (int j = 0; j < 8; j++) s[i][j] = 0.f;
        #pragma unroll
        for (int d = 0; d < 32; d++) {
            float qv[8], kv[8];
            *(float4*)(qv)     = *(const float4*)&QS(d, ty * 8);
            *(float4*)(qv + 4) = *(const float4*)&QS(d, ty * 8 + 4);
            *(float4*)(kv)     = *(const float4*)&KS(d, tx * 8);
            *(float4*)(kv + 4) = *(const float4*)&KS(d, tx * 8 + 4);
            #pragma unroll
            for (int i = 0; i < 8; i++)
                #pragma unroll
                for (int j = 0; j < 8; j++)
                    s[i][j] += qv[i] * kv[j];
        }
        // mask invalid keys
        int kbase = jt * KT + tx * 8;
        #pragma unroll
        for (int j = 0; j < 8; j++) {
            if (kbase + j >= NQ)
                #pragma unroll
                for (int i = 0; i < 8; i++) s[i][j] = -1e30f;
        }

        // ---- online softmax (row = ty*8+i; reduce over tx lanes 0..7) ----
        #pragma unroll
        for (int i = 0; i < 8; i++) {
            float mx = s[i][0];
            #pragma unroll
            for (int j = 1; j < 8; j++) mx = fmaxf(mx, s[i][j]);
            mx = fmaxf(mx, __shfl_xor_sync(full, mx, 1));
            mx = fmaxf(mx, __shfl_xor_sync(full, mx, 2));
            mx = fmaxf(mx, __shfl_xor_sync(full, mx, 4));
            float newm = fmaxf(m_r[i], mx);
            fac[i] = __expf(m_r[i] - newm);
            float sum = 0.f;
            #pragma unroll
            for (int j = 0; j < 8; j++) {
                float p = __expf(s[i][j] - newm);
                s[i][j] = p;
                sum += p;
            }
            sum += __shfl_xor_sync(full, sum, 1);
            sum += __shfl_xor_sync(full, sum, 2);
            sum += __shfl_xor_sync(full, sum, 4);
            l_r[i] = l_r[i] * fac[i] + sum;
            m_r[i] = newm;
        }
        // ---- write P transposed: Ps[k][q] ----
        #pragma unroll
        for (int j = 0; j < 8; j++) {
            *(float4*)&PS(tx * 8 + j, ty * 8) =
                make_float4(s[0][j], s[1][j], s[2][j], s[3][j]);
            *(float4*)&PS(tx * 8 + j, ty * 8 + 4) =
                make_float4(s[4][j], s[5][j], s[6][j], s[7][j]);
        }
        __syncthreads();

        // ---- PV: O[q=ty*8+i][d=tx*4+dd] += sum_j P[q][j] * V[j][d] ----
        #pragma unroll
        for (int i = 0; i < 8; i++)
            #pragma unroll
            for (int d = 0; d < 4; d++) O[i][d] *= fac[i];
        #pragma unroll 4
        for (int j = 0; j < KT; j++) {
            float p[8], v[4];
            *(float4*)(p)     = *(const float4*)&PS(j, ty * 8);
            *(float4*)(p + 4) = *(const float4*)&PS(j, ty * 8 + 4);
            *(float4*)(v)     = *(const float4*)&VS(j, tx * 4);
            #pragma unroll
            for (int i = 0; i < 8; i++)
                #pragma unroll
                for (int d = 0; d < 4; d++)
                    O[i][d] += p[i] * v[d];
        }
    }

    // ---- write out: out[b*NQ+q][h*32 + tx*4 + d] ----
    #pragma unroll
    for (int i = 0; i < 8; i++) {
        int q = qt * QT + ty * 8 + i;
        if (q >= NQ) continue;
        float inv = 1.f / l_r[i];
        float* dst = out + ((size_t)(b * NQ + q)) * DD + h * HD + tx * 4;
        *(float4*)dst = make_float4(O[i][0] * inv, O[i][1] * inv,
                                    O[i][2] * inv, O[i][3] * inv);
    }
}

// ---------------- deformable sampling: warp = (head), block = (b,q) ---------
__global__ void sample_kernel(const float* __restrict__ mem, const float* __restrict__ ref,
                              const float* __restrict__ offs, const float* __restrict__ wts,
                              float* __restrict__ fused) {
    int row = blockIdx.x;
    int b = row / NQ;
    int h = threadIdx.x >> 5;
    int lane = threadIdx.x & 31;
    const unsigned full = 0xffffffffu;
    float rx = ref[row * 2], ry = ref[row * 2 + 1];
    float gx = 0.f, gy = 0.f, wl = 0.f;
    if (lane < PP) {
        float ox = offs[(size_t)row * (HH * PP * 2) + h * (PP * 2) + lane * 2];
        float oy = offs[(size_t)row * (HH * PP * 2) + h * (PP * 2) + lane * 2 + 1];
        gx = (rx + tanhf(ox) * 0.2f) * (float)BEV - 0.5f;
        gy = (ry + tanhf(oy) * 0.2f) * (float)BEV - 0.5f;
        wl = wts[(size_t)row * (HH * PP) + h * PP + lane];
    }
    float m = wl;
    m = fmaxf(m, __shfl_xor_sync(full, m, 1));
    m = fmaxf(m, __shfl_xor_sync(full, m, 2));
    float e = __expf(wl - m);
    float ssum = e;
    ssum += __shfl_xor_sync(full, ssum, 1);
    ssum += __shfl_xor_sync(full, ssum, 2);
    float w = e / ssum;
    const float* mb = mem + (size_t)b * (BEV * BEV) * DD + h * HD + lane;
    float acc = 0.f;
    #pragma unroll
    for (int p = 0; p < PP; p++) {
        float px = __shfl_sync(full, gx, p);
        float py = __shfl_sync(full, gy, p);
        float pw = __shfl_sync(full, w, p);
        float x0f = floorf(px), y0f = floorf(py);
        float wx1 = px - x0f, wy1 = py - y0f;
        float wx0 = 1.f - wx1, wy0 = 1.f - wy1;
        int x0 = (int)x0f, y0 = (int)y0f;
        bool xv0 = (x0 >= 0) && (x0 < BEV);
        bool xv1 = (x0 + 1 >= 0) && (x0 + 1 < BEV);
        bool yv0 = (y0 >= 0) && (y0 < BEV);
        bool yv1 = (y0 + 1 >= 0) && (y0 + 1 < BEV);
        float v = 0.f;
        if (yv0) {
            if (xv0) v += wx0 * wy0 * mb[(size_t)(y0 * BEV + x0) * DD];
            if (xv1) v += wx1 * wy0 * mb[(size_t)(y0 * BEV + x0 + 1) * DD];
        }
        if (yv1) {
            if (xv0) v += wx0 * wy1 * mb[(size_t)((y0 + 1) * BEV + x0) * DD];
            if (xv1) v += wx1 * wy1 * mb[(size_t)((y0 + 1) * BEV + x0 + 1) * DD];
        }
        acc += pw * v;
    }
    fused[(size_t)row * DD + h * HD + lane] = acc;
}

// ---------------- host launcher ---------------------------------------------
extern "C" void kernel_launch(void* const* d_in, const int* in_sizes, int n_in,
                              void* d_out, int out_size) {
    const float* query = (const float*)d_in[0];
    const float* memory = (const float*)d_in[1];
    const float* refp  = (const float*)d_in[2];
    const float* qpos  = (const float*)d_in[3];
    const float* in_w  = (const float*)d_in[4];
    const float* in_b  = (const float*)d_in[5];
    const float* out_w = (const float*)d_in[6];
    const float* out_b = (const float*)d_in[7];
    const float* off_w = (const float*)d_in[8];
    const float* off_b = (const float*)d_in[9];
    const float* wt_w  = (const float*)d_in[10];
    const float* wt_b  = (const float*)d_in[11];
    const float* co_w  = (const float*)d_in[12];
    const float* co_b  = (const float*)d_in[13];
    const float* f_w1  = (const float*)d_in[14];
    const float* f_b1  = (const float*)d_in[15];
    const float* f_w2  = (const float*)d_in[16];
    const float* f_b2  = (const float*)d_in[17];
    const float* n1s   = (const float*)d_in[18];
    const float* n1b   = (const float*)d_in[19];
    const float* n2s   = (const float*)d_in[20];
    const float* n2b   = (const float*)d_in[21];
    const float* n3s   = (const float*)d_in[22];
    const float* n3b   = (const float*)d_in[23];

    float *qin, *qkv, *attn, *q1, *q2, *offs, *wts, *fused, *qq2, *q3, *mid;
    cudaGetSymbolAddress((void**)&qin,   g_qin);
    cudaGetSymbolAddress((void**)&qkv,   g_qkv);
    cudaGetSymbolAddress((void**)&attn,  g_attn);
    cudaGetSymbolAddress((void**)&q1,    g_q1);
    cudaGetSymbolAddress((void**)&q2,    g_q2);
    cudaGetSymbolAddress((void**)&offs,  g_offs);
    cudaGetSymbolAddress((void**)&wts,   g_wts);
    cudaGetSymbolAddress((void**)&fused, g_fused);
    cudaGetSymbolAddress((void**)&qq2,   g_qq2);
    cudaGetSymbolAddress((void**)&q3,    g_q3);
    cudaGetSymbolAddress((void**)&mid,   g_mid);

    const int M = MROWS;
    const int MT128 = (M + 127) / 128;   // 57
    const int MT64  = (M + 63) / 64;     // 113
    const int ATTN_SMEM = (32 * 132 + 32 * 68 + 64 * 36 + 64 * 132) * 4;  // 68608 B
    cudaFuncSetAttribute(attn2_kernel, cudaFuncAttributeMaxDynamicSharedMemorySize,
                         ATTN_SMEM);

    // 1. q_in = LN(query + query_pos)
    add_ln_kernel<<<M, 256>>>(query, qpos, n1s, n1b, qin);
    // 2. qkv = q_in @ in_w^T + in_b
    gemm128<<<dim3(6, MT128), 256>>>(qin, in_w, in_b, nullptr, qkv, M, 768, 256, 0);
    // 3. self-attention
    attn2_kernel<<<dim3((NQ + QT - 1) / QT, HH, BB), 128, ATTN_SMEM>>>(qkv, attn);
    // 4. q1 = attn @ out_w^T + out_b + query
    gemm128<<<dim3(2, MT128), 256>>>(attn, out_w, out_b, query, q1, M, 256, 256, 0);
    // 5. q2 = LN(q1 + query_pos)
    add_ln_kernel<<<M, 256>>>(q1, qpos, n2s, n2b, q2);
    // 6/7. offset + weight heads
    gemm_nt<<<dim3(1, MT64), 256>>>(q2, off_w, off_b, nullptr, offs, M, 64, 256, 0);
    gemm_nt<<<dim3(1, MT64), 256>>>(q2, wt_w, wt_b, nullptr, wts, M, 32, 256, 0);
    // 8. deformable BEV sampling -> fused
    sample_kernel<<<M, 256>>>(memory, refp, offs, wts, fused);
    // 9. qq2 = fused @ co_w^T + co_b + q1
    gemm128<<<dim3(2, MT128), 256>>>(fused, co_w, co_b, q1, qq2, M, 256, 256, 0);
    // 10. q3 = LN(qq2)
    add_ln_kernel<<<M, 256>>>(qq2, nullptr, n3s, n3b, q3);
    // 11. mid = relu(q3 @ f_w1^T + f_b1)
    gemm128<<<dim3(4, MT128), 256>>>(q3, f_w1, f_b1, nullptr, mid, M, 512, 256, 1);
    // 12. out = mid @ f_w2^T + f_b2 + qq2
    gemm128<<<dim3(2, MT128), 256>>>(mid, f_w2, f_b2, qq2, (float*)d_out, M, 256, 512, 0);
    (void)in_sizes; (void)n_in; (void)out_size;
}

// round 3
// speedup vs baseline: 2.0204x; 1.3189x over previous
#include <cuda_runtime.h>
#include <cuda_bf16.h>
#include <math.h>
#include <stdint.h>

// Problem constants
#define BB    8
#define NQ    900
#define DD    256
#define HH    8
#define HD    32
#define PP    4
#define BEV   200
#define FFN   512
#define MROWS (BB * NQ)          // 7200

// ---------------- scratch (allocation-free: __device__ globals) -------------
__device__ float g_qin  [MROWS * DD];
__device__ float g_qkv  [MROWS * 3 * DD];
__device__ float g_attn [MROWS * DD];
__device__ float g_q1   [MROWS * DD];
__device__ float g_q2   [MROWS * DD];
__device__ float g_offs [MROWS * HH * PP * 2];
__device__ float g_wts  [MROWS * HH * PP];
__device__ float g_fused[MROWS * DD];
__device__ float g_qq2  [MROWS * DD];
__device__ float g_q3   [MROWS * DD];
__device__ float g_mid  [MROWS * FFN];

// ---------------- block reduce helper ---------------------------------------
__inline__ __device__ float block_reduce_sum_256(float v, float* sh) {
    int lane = threadIdx.x & 31, w = threadIdx.x >> 5;
    #pragma unroll
    for (int o = 16; o; o >>= 1) v += __shfl_xor_sync(0xffffffffu, v, o);
    if (lane == 0) sh[w] = v;
    __syncthreads();
    if (w == 0) {
        float t = (lane < 8) ? sh[lane] : 0.f;
        #pragma unroll
        for (int o = 4; o; o >>= 1) t += __shfl_xor_sync(0xffffffffu, t, o);
        if (lane == 0) sh[0] = t;
    }
    __syncthreads();
    float r = sh[0];
    __syncthreads();
    return r;
}

// ---------------- fused add + LayerNorm (rows of 256) -----------------------
__global__ void add_ln_kernel(const float* __restrict__ a, const float* __restrict__ b,
                              const float* __restrict__ s, const float* __restrict__ bias,
                              float* __restrict__ out) {
    __shared__ float sh[8];
    int row = blockIdx.x, t = threadIdx.x;
    size_t idx = (size_t)row * DD + t;
    float x = a[idx] + (b ? b[idx] : 0.f);
    float mean = block_reduce_sum_256(x, sh) * (1.f / DD);
    float xc = x - mean;
    float var = block_reduce_sum_256(xc * xc, sh) * (1.f / DD);
    out[idx] = xc * rsqrtf(var + 1e-5f) * s[t] + bias[t];
}

// ---------------- tf32 -> u32 conversion -------------------------------------
__device__ __forceinline__ uint32_t f2tf32(float f) {
    uint32_t u;
    asm("cvt.rna.tf32.f32 %0, %1;" : "=r"(u) : "f"(f));
    return u;
}

__device__ __forceinline__ void mma1688(float* d, const uint32_t* a, const uint32_t* b) {
    asm volatile(
        "mma.sync.aligned.m16n8k8.row.col.f32.tf32.tf32.f32 "
        "{%0,%1,%2,%3}, {%4,%5,%6,%7}, {%8,%9}, {%0,%1,%2,%3};\n"
        : "+f"(d[0]), "+f"(d[1]), "+f"(d[2]), "+f"(d[3])
        : "r"(a[0]), "r"(a[1]), "r"(a[2]), "r"(a[3]), "r"(b[0]), "r"(b[1]));
}

// ---------------- tensor-core NT GEMM: C = A[M,K] * B[N,K]^T + epi ----------
// 128x128 tile, BK=16, 256 thr (8 warps, 2x4), tf32 mma m16n8k8, fp32 acc.
// Requires N % 128 == 0, K % 16 == 0.
#define SSTR 20   // smem row stride (16 k + 4 pad): conflict-free frag loads
__global__ __launch_bounds__(256)
void gemm_tc(const float* __restrict__ A, const float* __restrict__ B,
             const float* __restrict__ bias, const float* __restrict__ resid,
             float* __restrict__ C, int M, int N, int K, int relu) {
    __shared__ uint32_t As[128 * SSTR];
    __shared__ uint32_t Bs[128 * SSTR];
    const int tid = threadIdx.x;
    const int lane = tid & 31, wid = tid >> 5;
    const int g = lane >> 2, tg = lane & 3;
    const int wm = (wid >> 2) * 64, wn = (wid & 3) * 32;
    const int bm = blockIdx.y * 128, bn = blockIdx.x * 128;

    // global load slots: idx = tid + 256*i -> row = idx>>2 (0..127), kq = (idx&3)*4
    const int row0 = tid >> 2, kq0 = (tid & 3) * 4;
    const int row1 = (tid + 256) >> 2, kq1 = kq0;   // same kq, row+64

    float4 pa[2], pb[2];
    const float4 z4 = make_float4(0.f, 0.f, 0.f, 0.f);

    // prologue: load k0 = 0
    {
        int gm0 = bm + row0, gm1 = bm + row1;
        pa[0] = (gm0 < M) ? *(const float4*)(A + (size_t)gm0 * K + kq0) : z4;
        pa[1] = (gm1 < M) ? *(const float4*)(A + (size_t)gm1 * K + kq1) : z4;
        pb[0] = *(const float4*)(B + (size_t)(bn + row0) * K + kq0);
        pb[1] = *(const float4*)(B + (size_t)(bn + row1) * K + kq1);
    }

    float acc[4][4][4];
    #pragma unroll
    for (int mi = 0; mi < 4; mi++)
        #pragma unroll
        for (int ni = 0; ni < 4; ni++)
            #pragma unroll
            for (int r = 0; r < 4; r++) acc[mi][ni][r] = 0.f;

    for (int k0 = 0; k0 < K; k0 += 16) {
        // store current stage (tf32-converted)
        {
            uint4 ua0 = make_uint4(f2tf32(pa[0].x), f2tf32(pa[0].y), f2tf32(pa[0].z), f2tf32(pa[0].w));
            uint4 ua1 = make_uint4(f2tf32(pa[1].x), f2tf32(pa[1].y), f2tf32(pa[1].z), f2tf32(pa[1].w));
            uint4 ub0 = make_uint4(f2tf32(pb[0].x), f2tf32(pb[0].y), f2tf32(pb[0].z), f2tf32(pb[0].w));
            uint4 ub1 = make_uint4(f2tf32(pb[1].x), f2tf32(pb[1].y), f2tf32(pb[1].z), f2tf32(pb[1].w));
            *(uint4*)&As[row0 * SSTR + kq0] = ua0;
            *(uint4*)&As[row1 * SSTR + kq1] = ua1;
            *(uint4*)&Bs[row0 * SSTR + kq0] = ub0;
            *(uint4*)&Bs[row1 * SSTR + kq1] = ub1;
        }
        __syncthreads();
        // prefetch next stage
        if (k0 + 16 < K) {
            int kn = k0 + 16;
            int gm0 = bm + row0, gm1 = bm + row1;
            pa[0] = (gm0 < M) ? *(const float4*)(A + (size_t)gm0 * K + kn + kq0) : z4;
            pa[1] = (gm1 < M) ? *(const float4*)(A + (size_t)gm1 * K + kn + kq1) : z4;
            pb[0] = *(const float4*)(B + (size_t)(bn + row0) * K + kn + kq0);
            pb[1] = *(const float4*)(B + (size_t)(bn + row1) * K + kn + kq1);
        }
        // compute 2 k8-steps
        #pragma unroll
        for (int k8 = 0; k8 < 2; k8++) {
            uint32_t af[4][4], bf[4][2];
            #pragma unroll
            for (int mi = 0; mi < 4; mi++) {
                const uint32_t* base = &As[(wm + mi * 16 + g) * SSTR + k8 * 8 + tg];
                af[mi][0] = base[0];
                af[mi][1] = base[8 * SSTR];
                af[mi][2] = base[4];
                af[mi][3] = base[8 * SSTR + 4];
            }
            #pragma unroll
            for (int ni = 0; ni < 4; ni++) {
                const uint32_t* base = &Bs[(wn + ni * 8 + g) * SSTR + k8 * 8 + tg];
                bf[ni][0] = base[0];
                bf[ni][1] = base[4];
            }
            #pragma unroll
            for (int mi = 0; mi < 4; mi++)
                #pragma unroll
                for (int ni = 0; ni < 4; ni++)
                    mma1688(acc[mi][ni], af[mi], bf[ni]);
        }
        __syncthreads();
    }

    // epilogue: d0=C[g][2tg], d1=C[g][2tg+1], d2=C[g+8][2tg], d3=C[g+8][2tg+1]
    #pragma unroll
    for (int ni = 0; ni < 4; ni++) {
        int c = bn + wn + ni * 8 + 2 * tg;
        float b0 = bias ? bias[c] : 0.f;
        float b1 = bias ? bias[c + 1] : 0.f;
        #pragma unroll
        for (int mi = 0; mi < 4; mi++) {
            int r0 = bm + wm + mi * 16 + g;
            int r1 = r0 + 8;
            float v0 = acc[mi][ni][0] + b0, v1 = acc[mi][ni][1] + b1;
            float v2 = acc[mi][ni][2] + b0, v3 = acc[mi][ni][3] + b1;
            if (relu) {
                v0 = fmaxf(v0, 0.f); v1 = fmaxf(v1, 0.f);
                v2 = fmaxf(v2, 0.f); v3 = fmaxf(v3, 0.f);
            }
            if (r0 < M) {
                if (resid) {
                    float2 rr = *(const float2*)(resid + (size_t)r0 * N + c);
                    v0 += rr.x; v1 += rr.y;
                }
                *(float2*)(C + (size_t)r0 * N + c) = make_float2(v0, v1);
            }
            if (r1 < M) {
                if (resid) {
                    float2 rr = *(const float2*)(resid + (size_t)r1 * N + c);
                    v2 += rr.x; v3 += rr.y;
                }
                *(float2*)(C + (size_t)r1 * N + c) = make_float2(v2, v3);
            }
        }
    }
}

// ---------------- small NT GEMM (N=64/32 heads): 64x64 tile, 4x4 micro ------
__global__ void gemm_nt(const float* __restrict__ A, const float* __restrict__ B,
                        const float* __restrict__ bias, const float* __restrict__ resid,
                        float* __restrict__ C, int M, int N, int K, int relu) {
    __shared__ float As[16][68];
    __shared__ float Bs[16][68];
    int tid = threadIdx.x;
    int tx = tid & 15, ty = tid >> 4;
    int bm = blockIdx.y * 64, bn = blockIdx.x * 64;
    int lm = tid >> 2;
    int kq = (tid & 3) * 4;
    float acc[4][4] = {};
    for (int k0 = 0; k0 < K; k0 += 16) {
        int gm = bm + lm;
        float4 va = make_float4(0.f, 0.f, 0.f, 0.f);
        if (gm < M) va = *(const float4*)(A + (size_t)gm * K + k0 + kq);
        As[kq + 0][lm] = va.x; As[kq + 1][lm] = va.y;
        As[kq + 2][lm] = va.z; As[kq + 3][lm] = va.w;
        int gn = bn + lm;
        float4 vb = make_float4(0.f, 0.f, 0.f, 0.f);
        if (gn < N) vb = *(const float4*)(B + (size_t)gn * K + k0 + kq);
        Bs[kq + 0][lm] = vb.x; Bs[kq + 1][lm] = vb.y;
        Bs[kq + 2][lm] = vb.z; Bs[kq + 3][lm] = vb.w;
        __syncthreads();
        #pragma unroll
        for (int k = 0; k < 16; k++) {
            float4 a4 = *(const float4*)&As[k][ty * 4];
            float4 b4 = *(const float4*)&Bs[k][tx * 4];
            float af[4] = {a4.x, a4.y, a4.z, a4.w};
            float bf[4] = {b4.x, b4.y, b4.z, b4.w};
            #pragma unroll
            for (int i = 0; i < 4; i++)
                #pragma unroll
                for (int j = 0; j < 4; j++)
                    acc[i][j] += af[i] * bf[j];
        }
        __syncthreads();
    }
    #pragma unroll
    for (int i = 0; i < 4; i++) {
        int r = bm + ty * 4 + i;
        if (r >= M) continue;
        #pragma unroll
        for (int j = 0; j < 4; j++) {
            int c = bn + tx * 4 + j;
            if (c >= N) continue;
            float v = acc[i][j];
            if (bias) v += bias[c];
            if (relu) v = fmaxf(v, 0.f);
            if (resid) v += resid[(size_t)r * N + c];
            C[(size_t)r * N + c] = v;
        }
    }
}

// ---------------- fused self-attention v2 ------------------------------------
// 128-query x 64-key tiles, HD=32, 128 threads.
#define QT 128
#define KT 64
#define QS(d,q) Qs[(d) * 132 + (q)]
#define KS(d,k) Ks[(d) * 68 + (k)]
#define VS(k,d) Vs[(k) * 36 + (d)]
#define PS(k,q) Ps[(k) * 132 + (q)]

__global__ __launch_bounds__(128)
void attn2_kernel(const float* __restrict__ qkv, float* __restrict__ out) {
    extern __shared__ float sm[];
    float* Qs = sm;
    float* Ks = Qs + 32 * 132;
    float* Vs = Ks + 32 * 68;
    float* Ps = Vs + 64 * 36;

    const int b = blockIdx.z, h = blockIdx.y, qt = blockIdx.x;
    const int tid = threadIdx.x;
    const int ty = tid >> 3;
    const int tx = tid & 7;
    const float scale = 0.17677669529663687f;
    const unsigned full = 0xffffffffu;

    {
        int q = qt * QT + tid;
        if (q < NQ) {
            const float* src = qkv + ((size_t)(b * NQ + q)) * 768 + h * HD;
            #pragma unroll
            for (int d4 = 0; d4 < 32; d4 += 4) {
                float4 v = *(const float4*)(src + d4);
                QS(d4 + 0, tid) = v.x * scale; QS(d4 + 1, tid) = v.y * scale;
                QS(d4 + 2, tid) = v.z * scale; QS(d4 + 3, tid) = v.w * scale;
            }
        } else {
            #pragma unroll
            for (int d = 0; d < 32; d++) QS(d, tid) = 0.f;
        }
    }

    float m_r[8], l_r[8], fac[8];
    float O[8][4];
    #pragma unroll
    for (int i = 0; i < 8; i++) {
        m_r[i] = -INFINITY; l_r[i] = 0.f;
        #pragma unroll
        for (int d = 0; d < 4; d++) O[i][d] = 0.f;
    }

    const int NKT = (NQ + KT - 1) / KT;
    for (int jt = 0; jt < NKT; jt++) {
        __syncthreads();
        if (tid < 64) {
            int kk = jt * KT + tid;
            if (kk < NQ) {
                const float* src = qkv + ((size_t)(b * NQ + kk)) * 768 + 256 + h * HD;
                #pragma unroll
                for (int d4 = 0; d4 < 32; d4 += 4) {
                    float4 v = *(const float4*)(src + d4);
                    KS(d4 + 0, tid) = v.x; KS(d4 + 1, tid) = v.y;
                    KS(d4 + 2, tid) = v.z; KS(d4 + 3, tid) = v.w;
                }
            } else {
                #pragma unroll
                for (int d = 0; d < 32; d++) KS(d, tid) = 0.f;
            }
        } else {
            int kk = jt * KT + tid - 64;
            float* dst = &VS(tid - 64, 0);
            if (kk < NQ) {
                const float* src = qkv + ((size_t)(b * NQ + kk)) * 768 + 512 + h * HD;
                #pragma unroll
                for (int d4 = 0; d4 < 32; d4 += 4)
                    *(float4*)(dst + d4) = *(const float4*)(src + d4);
            } else {
                #pragma unroll
                for (int d = 0; d < 32; d++) dst[d] = 0.f;
            }
        }
        __syncthreads();

        float s[8][8];
        #pragma unroll
        for (int i = 0; i < 8; i++)
            #pragma unroll
            for (int j = 0; j < 8; j++) s[i][j] = 0.f;
        #pragma unroll
        for (int d = 0; d < 32; d++) {
            float qv[8], kv[8];
            *(float4*)(qv)     = *(const float4*)&QS(d, ty * 8);
            *(float4*)(qv + 4) = *(const float4*)&QS(d, ty * 8 + 4);
            *(float4*)(kv)     = *(const float4*)&KS(d, tx * 8);
            *(float4*)(kv + 4) = *(const float4*)&KS(d, tx * 8 + 4);
            #pragma unroll
            for (int i = 0; i < 8; i++)
                #pragma unroll
                for (int j = 0; j < 8; j++)
                    s[i][j] += qv[i] * kv[j];
        }
        int kbase = jt * KT + tx * 8;
        #pragma unroll
        for (int j = 0; j < 8; j++) {
            if (kbase + j >= NQ)
                #pragma unroll
                for (int i = 0; i < 8; i++) s[i][j] = -1e30f;
        }

        #pragma unroll
        for (int i = 0; i < 8; i++) {
            float mx = s[i][0];
            #pragma unroll
            for (int j = 1; j < 8; j++) mx = fmaxf(mx, s[i][j]);
            mx = fmaxf(mx, __shfl_xor_sync(full, mx, 1));
            mx = fmaxf(mx, __shfl_xor_sync(full, mx, 2));
            mx = fmaxf(mx, __shfl_xor_sync(full, mx, 4));
            float newm = fmaxf(m_r[i], mx);
            fac[i] = __expf(m_r[i] - newm);
            float sum = 0.f;
            #pragma unroll
            for (int j = 0; j < 8; j++) {
                float p = __expf(s[i][j] - newm);
                s[i][j] = p;
                sum += p;
            }
            sum += __shfl_xor_sync(full, sum, 1);
            sum += __shfl_xor_sync(full, sum, 2);
            sum += __shfl_xor_sync(full, sum, 4);
            l_r[i] = l_r[i] * fac[i] + sum;
            m_r[i] = newm;
        }
        #pragma unroll
        for (int j = 0; j < 8; j++) {
            *(float4*)&PS(tx * 8 + j, ty * 8) =
                make_float4(s[0][j], s[1][j], s[2][j], s[3][j]);
            *(float4*)&PS(tx * 8 + j, ty * 8 + 4) =
                make_float4(s[4][j], s[5][j], s[6][j], s[7][j]);
        }
        __syncthreads();

        #pragma unroll
        for (int i = 0; i < 8; i++)
            #pragma unroll
            for (int d = 0; d < 4; d++) O[i][d] *= fac[i];
        #pragma unroll 4
        for (int j = 0; j < KT; j++) {
            float p[8], v[4];
            *(float4*)(p)     = *(const float4*)&PS(j, ty * 8);
            *(float4*)(p + 4) = *(const float4*)&PS(j, ty * 8 + 4);
            *(float4*)(v)     = *(const float4*)&VS(j, tx * 4);
            #pragma unroll
            for (int i = 0; i < 8; i++)
                #pragma unroll
                for (int d = 0; d < 4; d++)
                    O[i][d] += p[i] * v[d];
        }
    }

    #pragma unroll
    for (int i = 0; i < 8; i++) {
        int q = qt * QT + ty * 8 + i;
        if (q >= NQ) continue;
        float inv = 1.f / l_r[i];
        float* dst = out + ((size_t)(b * NQ + q)) * DD + h * HD + tx * 4;
        *(float4*)dst = make_float4(O[i][0] * inv, O[i][1] * inv,
                                    O[i][2] * inv, O[i][3] * inv);
    }
}

// ---------------- deformable sampling: warp = (head), block = (b,q) ---------
__global__ void sample_kernel(const float* __restrict__ mem, const float* __restrict__ ref,
                              const float* __restrict__ offs, const float* __restrict__ wts,
                              float* __restrict__ fused) {
    int row = blockIdx.x;
    int b = row / NQ;
    int h = threadIdx.x >> 5;
    int lane = threadIdx.x & 31;
    const unsigned full = 0xffffffffu;
    float rx = ref[row * 2], ry = ref[row * 2 + 1];
    float gx = 0.f, gy = 0.f, wl = 0.f;
    if (lane < PP) {
        float ox = offs[(size_t)row * (HH * PP * 2) + h * (PP * 2) + lane * 2];
        float oy = offs[(size_t)row * (HH * PP * 2) + h * (PP * 2) + lane * 2 + 1];
        gx = (rx + tanhf(ox) * 0.2f) * (float)BEV - 0.5f;
        gy = (ry + tanhf(oy) * 0.2f) * (float)BEV - 0.5f;
        wl = wts[(size_t)row * (HH * PP) + h * PP + lane];
    }
    float m = wl;
    m = fmaxf(m, __shfl_xor_sync(full, m, 1));
    m = fmaxf(m, __shfl_xor_sync(full, m, 2));
    float e = __expf(wl - m);
    float ssum = e;
    ssum += __shfl_xor_sync(full, ssum, 1);
    ssum += __shfl_xor_sync(full, ssum, 2);
    float w = e / ssum;
    const float* mb = mem + (size_t)b * (BEV * BEV) * DD + h * HD + lane;
    float acc = 0.f;
    #pragma unroll
    for (int p = 0; p < PP; p++) {
        float px = __shfl_sync(full, gx, p);
        float py = __shfl_sync(full, gy, p);
        float pw = __shfl_sync(full, w, p);
        float x0f = floorf(px), y0f = floorf(py);
        float wx1 = px - x0f, wy1 = py - y0f;
        float wx0 = 1.f - wx1, wy0 = 1.f - wy1;
        int x0 = (int)x0f, y0 = (int)y0f;
        bool xv0 = (x0 >= 0) && (x0 < BEV);
        bool xv1 = (x0 + 1 >= 0) && (x0 + 1 < BEV);
        bool yv0 = (y0 >= 0) && (y0 < BEV);
        bool yv1 = (y0 + 1 >= 0) && (y0 + 1 < BEV);
        float v = 0.f;
        if (yv0) {
            if (xv0) v += wx0 * wy0 * mb[(size_t)(y0 * BEV + x0) * DD];
            if (xv1) v += wx1 * wy0 * mb[(size_t)(y0 * BEV + x0 + 1) * DD];
        }
        if (yv1) {
            if (xv0) v += wx0 * wy1 * mb[(size_t)((y0 + 1) * BEV + x0) * DD];
            if (xv1) v += wx1 * wy1 * mb[(size_t)((y0 + 1) * BEV + x0 + 1) * DD];
        }
        acc += pw * v;
    }
    fused[(size_t)row * DD + h * HD + lane] = acc;
}

// ---------------- host launcher ---------------------------------------------
extern "C" void kernel_launch(void* const* d_in, const int* in_sizes, int n_in,
                              void* d_out, int out_size) {
    const float* query = (const float*)d_in[0];
    const float* memory = (const float*)d_in[1];
    const float* refp  = (const float*)d_in[2];
    const float* qpos  = (const float*)d_in[3];
    const float* in_w  = (const float*)d_in[4];
    const float* in_b  = (const float*)d_in[5];
    const float* out_w = (const float*)d_in[6];
    const float* out_b = (const float*)d_in[7];
    const float* off_w = (const float*)d_in[8];
    const float* off_b = (const float*)d_in[9];
    const float* wt_w  = (const float*)d_in[10];
    const float* wt_b  = (const float*)d_in[11];
    const float* co_w  = (const float*)d_in[12];
    const float* co_b  = (const float*)d_in[13];
    const float* f_w1  = (const float*)d_in[14];
    const float* f_b1  = (const float*)d_in[15];
    const float* f_w2  = (const float*)d_in[16];
    const float* f_b2  = (const float*)d_in[17];
    const float* n1s   = (const float*)d_in[18];
    const float* n1b   = (const float*)d_in[19];
    const float* n2s   = (const float*)d_in[20];
    const float* n2b   = (const float*)d_in[21];
    const float* n3s   = (const float*)d_in[22];
    const float* n3b   = (const float*)d_in[23];

    float *qin, *qkv, *attn, *q1, *q2, *offs, *wts, *fused, *qq2, *q3, *mid;
    cudaGetSymbolAddress((void**)&qin,   g_qin);
    cudaGetSymbolAddress((void**)&qkv,   g_qkv);
    cudaGetSymbolAddress((void**)&attn,  g_attn);
    cudaGetSymbolAddress((void**)&q1,    g_q1);
    cudaGetSymbolAddress((void**)&q2,    g_q2);
    cudaGetSymbolAddress((void**)&offs,  g_offs);
    cudaGetSymbolAddress((void**)&wts,   g_wts);
    cudaGetSymbolAddress((void**)&fused, g_fused);
    cudaGetSymbolAddress((void**)&qq2,   g_qq2);
    cudaGetSymbolAddress((void**)&q3,    g_q3);
    cudaGetSymbolAddress((void**)&mid,   g_mid);

    const int M = MROWS;
    const int MTC = (M + 127) / 128;     // 57
    const int MT64 = (M + 63) / 64;      // 113
    const int ATTN_SMEM = (32 * 132 + 32 * 68 + 64 * 36 + 64 * 132) * 4;  // 68608 B
    cudaFuncSetAttribute(attn2_kernel, cudaFuncAttributeMaxDynamicSharedMemorySize,
                         ATTN_SMEM);

    // 1. q_in = LN(query + query_pos)
    add_ln_kernel<<<M, 256>>>(query, qpos, n1s, n1b, qin);
    // 2. qkv = q_in @ in_w^T + in_b
    gemm_tc<<<dim3(6, MTC), 256>>>(qin, in_w, in_b, nullptr, qkv, M, 768, 256, 0);
    // 3. self-attention
    attn2_kernel<<<dim3((NQ + QT - 1) / QT, HH, BB), 128, ATTN_SMEM>>>(qkv, attn);
    // 4. q1 = attn @ out_w^T + out_b + query
    gemm_tc<<<dim3(2, MTC), 256>>>(attn, out_w, out_b, query, q1, M, 256, 256, 0);
    // 5. q2 = LN(q1 + query_pos)
    add_ln_kernel<<<M, 256>>>(q1, qpos, n2s, n2b, q2);
    // 6/7. offset + weight heads
    gemm_nt<<<dim3(1, MT64), 256>>>(q2, off_w, off_b, nullptr, offs, M, 64, 256, 0);
    gemm_nt<<<dim3(1, MT64), 256>>>(q2, wt_w, wt_b, nullptr, wts, M, 32, 256, 0);
    // 8. deformable BEV sampling -> fused
    sample_kernel<<<M, 256>>>(memory, refp, offs, wts, fused);
    // 9. qq2 = fused @ co_w^T + co_b + q1
    gemm_tc<<<dim3(2, MTC), 256>>>(fused, co_w, co_b, q1, qq2, M, 256, 256, 0);
    // 10. q3 = LN(qq2)
    add_ln_kernel<<<M, 256>>>(qq2, nullptr, n3s, n3b, q3);
    // 11. mid = relu(q3 @ f_w1^T + f_b1)
    gemm_tc<<<dim3(4, MTC), 256>>>(q3, f_w1, f_b1, nullptr, mid, M, 512, 256, 1);
    // 12. out = mid @ f_w2^T + f_b2 + qq2
    gemm_tc<<<dim3(2, MTC), 256>>>(mid, f_w2, f_b2, qq2, (float*)d_out, M, 256, 512, 0);
    (void)in_sizes; (void)n_in; (void)out_size;
}

// round 4
// speedup vs baseline: 3.3502x; 1.6582x over previous
#include <cuda_runtime.h>
#include <cuda_bf16.h>
#include <math.h>
#include <stdint.h>

// Problem constants
#define BB    8
#define NQ    900
#define DD    256
#define HH    8
#define HD    32
#define PP    4
#define BEV   200
#define FFN   512
#define MROWS (BB * NQ)          // 7200

// ---------------- scratch (allocation-free: __device__ globals) -------------
__device__ float g_qin  [MROWS * DD];
__device__ float g_qkv  [MROWS * 3 * DD];
__device__ float g_attn [MROWS * DD];
__device__ float g_q1   [MROWS * DD];
__device__ float g_q2   [MROWS * DD];
__device__ float g_offs [MROWS * HH * PP * 2];
__device__ float g_wts  [MROWS * HH * PP];
__device__ float g_fused[MROWS * DD];
__device__ float g_qq2  [MROWS * DD];
__device__ float g_q3   [MROWS * DD];
__device__ float g_mid  [MROWS * FFN];

// ---------------- block reduce helper ---------------------------------------
__inline__ __device__ float block_reduce_sum_256(float v, float* sh) {
    int lane = threadIdx.x & 31, w = threadIdx.x >> 5;
    #pragma unroll
    for (int o = 16; o; o >>= 1) v += __shfl_xor_sync(0xffffffffu, v, o);
    if (lane == 0) sh[w] = v;
    __syncthreads();
    if (w == 0) {
        float t = (lane < 8) ? sh[lane] : 0.f;
        #pragma unroll
        for (int o = 4; o; o >>= 1) t += __shfl_xor_sync(0xffffffffu, t, o);
        if (lane == 0) sh[0] = t;
    }
    __syncthreads();
    float r = sh[0];
    __syncthreads();
    return r;
}

// ---------------- fused add + LayerNorm (rows of 256) -----------------------
__global__ void add_ln_kernel(const float* __restrict__ a, const float* __restrict__ b,
                              const float* __restrict__ s, const float* __restrict__ bias,
                              float* __restrict__ out) {
    __shared__ float sh[8];
    int row = blockIdx.x, t = threadIdx.x;
    size_t idx = (size_t)row * DD + t;
    float x = a[idx] + (b ? b[idx] : 0.f);
    float mean = block_reduce_sum_256(x, sh) * (1.f / DD);
    float xc = x - mean;
    float var = block_reduce_sum_256(xc * xc, sh) * (1.f / DD);
    out[idx] = xc * rsqrtf(var + 1e-5f) * s[t] + bias[t];
}

// ---------------- tf32 helpers ----------------------------------------------
__device__ __forceinline__ uint32_t f2tf32(float f) {
    uint32_t u;
    asm("cvt.rna.tf32.f32 %0, %1;" : "=r"(u) : "f"(f));
    return u;
}

__device__ __forceinline__ void mma1688(float* d, const uint32_t* a, const uint32_t* b) {
    asm volatile(
        "mma.sync.aligned.m16n8k8.row.col.f32.tf32.tf32.f32 "
        "{%0,%1,%2,%3}, {%4,%5,%6,%7}, {%8,%9}, {%0,%1,%2,%3};\n"
        : "+f"(d[0]), "+f"(d[1]), "+f"(d[2]), "+f"(d[3])
        : "r"(a[0]), "r"(a[1]), "r"(a[2]), "r"(a[3]), "r"(b[0]), "r"(b[1]));
}

// ---------------- tensor-core NT GEMM: C = A[M,K] * B[N,K]^T + epi ----------
// 128x64 tile, BK=16, 256 thr (8 warps, 4x2), warp tile 32x32, 2 CTAs/SM.
// Requires N % 64 == 0, K % 16 == 0.
#define SSTR 20
__global__ __launch_bounds__(256, 2)
void gemm_tc(const float* __restrict__ A, const float* __restrict__ B,
             const float* __restrict__ bias, const float* __restrict__ resid,
             float* __restrict__ C, int M, int N, int K, int relu) {
    __shared__ uint32_t As[128 * SSTR];
    __shared__ uint32_t Bs[64 * SSTR];
    const int tid = threadIdx.x;
    const int lane = tid & 31, wid = tid >> 5;
    const int g = lane >> 2, tg = lane & 3;
    const int wm = (wid >> 1) * 32, wn = (wid & 1) * 32;
    const int bm = blockIdx.y * 128, bn = blockIdx.x * 64;

    const int rowA0 = tid >> 2, rowA1 = rowA0 + 64;
    const int rowB  = tid >> 2;            // 0..63
    const int kq    = (tid & 3) * 4;

    float4 pa[2], pb;
    const float4 z4 = make_float4(0.f, 0.f, 0.f, 0.f);

    {
        int gm0 = bm + rowA0, gm1 = bm + rowA1;
        pa[0] = (gm0 < M) ? *(const float4*)(A + (size_t)gm0 * K + kq) : z4;
        pa[1] = (gm1 < M) ? *(const float4*)(A + (size_t)gm1 * K + kq) : z4;
        pb    = *(const float4*)(B + (size_t)(bn + rowB) * K + kq);
    }

    float acc[2][4][4];
    #pragma unroll
    for (int mi = 0; mi < 2; mi++)
        #pragma unroll
        for (int ni = 0; ni < 4; ni++)
            #pragma unroll
            for (int r = 0; r < 4; r++) acc[mi][ni][r] = 0.f;

    for (int k0 = 0; k0 < K; k0 += 16) {
        *(uint4*)&As[rowA0 * SSTR + kq] =
            make_uint4(f2tf32(pa[0].x), f2tf32(pa[0].y), f2tf32(pa[0].z), f2tf32(pa[0].w));
        *(uint4*)&As[rowA1 * SSTR + kq] =
            make_uint4(f2tf32(pa[1].x), f2tf32(pa[1].y), f2tf32(pa[1].z), f2tf32(pa[1].w));
        *(uint4*)&Bs[rowB * SSTR + kq] =
            make_uint4(f2tf32(pb.x), f2tf32(pb.y), f2tf32(pb.z), f2tf32(pb.w));
        __syncthreads();
        if (k0 + 16 < K) {
            int kn = k0 + 16;
            int gm0 = bm + rowA0, gm1 = bm + rowA1;
            pa[0] = (gm0 < M) ? *(const float4*)(A + (size_t)gm0 * K + kn + kq) : z4;
            pa[1] = (gm1 < M) ? *(const float4*)(A + (size_t)gm1 * K + kn + kq) : z4;
            pb    = *(const float4*)(B + (size_t)(bn + rowB) * K + kn + kq);
        }
        #pragma unroll
        for (int k8 = 0; k8 < 2; k8++) {
            uint32_t af[2][4], bf[4][2];
            #pragma unroll
            for (int mi = 0; mi < 2; mi++) {
                const uint32_t* base = &As[(wm + mi * 16 + g) * SSTR + k8 * 8 + tg];
                af[mi][0] = base[0];
                af[mi][1] = base[8 * SSTR];
                af[mi][2] = base[4];
                af[mi][3] = base[8 * SSTR + 4];
            }
            #pragma unroll
            for (int ni = 0; ni < 4; ni++) {
                const uint32_t* base = &Bs[(wn + ni * 8 + g) * SSTR + k8 * 8 + tg];
                bf[ni][0] = base[0];
                bf[ni][1] = base[4];
            }
            #pragma unroll
            for (int mi = 0; mi < 2; mi++)
                #pragma unroll
                for (int ni = 0; ni < 4; ni++)
                    mma1688(acc[mi][ni], af[mi], bf[ni]);
        }
        __syncthreads();
    }

    #pragma unroll
    for (int ni = 0; ni < 4; ni++) {
        int c = bn + wn + ni * 8 + 2 * tg;
        float b0 = bias ? bias[c] : 0.f;
        float b1 = bias ? bias[c + 1] : 0.f;
        #pragma unroll
        for (int mi = 0; mi < 2; mi++) {
            int r0 = bm + wm + mi * 16 + g;
            int r1 = r0 + 8;
            float v0 = acc[mi][ni][0] + b0, v1 = acc[mi][ni][1] + b1;
            float v2 = acc[mi][ni][2] + b0, v3 = acc[mi][ni][3] + b1;
            if (relu) {
                v0 = fmaxf(v0, 0.f); v1 = fmaxf(v1, 0.f);
                v2 = fmaxf(v2, 0.f); v3 = fmaxf(v3, 0.f);
            }
            if (r0 < M) {
                if (resid) {
                    float2 rr = *(const float2*)(resid + (size_t)r0 * N + c);
                    v0 += rr.x; v1 += rr.y;
                }
                *(float2*)(C + (size_t)r0 * N + c) = make_float2(v0, v1);
            }
            if (r1 < M) {
                if (resid) {
                    float2 rr = *(const float2*)(resid + (size_t)r1 * N + c);
                    v2 += rr.x; v3 += rr.y;
                }
                *(float2*)(C + (size_t)r1 * N + c) = make_float2(v2, v3);
            }
        }
    }
}

// ---------------- small NT GEMM (N=32 weights head) --------------------------
__global__ void gemm_nt(const float* __restrict__ A, const float* __restrict__ B,
                        const float* __restrict__ bias, const float* __restrict__ resid,
                        float* __restrict__ C, int M, int N, int K, int relu) {
    __shared__ float As[16][68];
    __shared__ float Bs[16][68];
    int tid = threadIdx.x;
    int tx = tid & 15, ty = tid >> 4;
    int bm = blockIdx.y * 64, bn = blockIdx.x * 64;
    int lm = tid >> 2;
    int kq = (tid & 3) * 4;
    float acc[4][4] = {};
    for (int k0 = 0; k0 < K; k0 += 16) {
        int gm = bm + lm;
        float4 va = make_float4(0.f, 0.f, 0.f, 0.f);
        if (gm < M) va = *(const float4*)(A + (size_t)gm * K + k0 + kq);
        As[kq + 0][lm] = va.x; As[kq + 1][lm] = va.y;
        As[kq + 2][lm] = va.z; As[kq + 3][lm] = va.w;
        int gn = bn + lm;
        float4 vb = make_float4(0.f, 0.f, 0.f, 0.f);
        if (gn < N) vb = *(const float4*)(B + (size_t)gn * K + k0 + kq);
        Bs[kq + 0][lm] = vb.x; Bs[kq + 1][lm] = vb.y;
        Bs[kq + 2][lm] = vb.z; Bs[kq + 3][lm] = vb.w;
        __syncthreads();
        #pragma unroll
        for (int k = 0; k < 16; k++) {
            float4 a4 = *(const float4*)&As[k][ty * 4];
            float4 b4 = *(const float4*)&Bs[k][tx * 4];
            float af[4] = {a4.x, a4.y, a4.z, a4.w};
            float bf[4] = {b4.x, b4.y, b4.z, b4.w};
            #pragma unroll
            for (int i = 0; i < 4; i++)
                #pragma unroll
                for (int j = 0; j < 4; j++)
                    acc[i][j] += af[i] * bf[j];
        }
        __syncthreads();
    }
    #pragma unroll
    for (int i = 0; i < 4; i++) {
        int r = bm + ty * 4 + i;
        if (r >= M) continue;
        #pragma unroll
        for (int j = 0; j < 4; j++) {
            int c = bn + tx * 4 + j;
            if (c >= N) continue;
            float v = acc[i][j];
            if (bias) v += bias[c];
            if (relu) v = fmaxf(v, 0.f);
            if (resid) v += resid[(size_t)r * N + c];
            C[(size_t)r * N + c] = v;
        }
    }
}

// ---------------- tensor-core flash attention --------------------------------
// 64-query blocks, 4 warps (16 q each), 64-key tiles, HD=32. tf32 mma.
#define KSTR 36
#define VSTR 68
#define PSTR 68
__global__ __launch_bounds__(128)
void attn3_kernel(const float* __restrict__ qkv, float* __restrict__ out) {
    __shared__ float Ks[64 * KSTR];   // K tile [key][d]
    __shared__ float Vs[32 * VSTR];   // V tile transposed [d][key]
    __shared__ float Ps[64 * PSTR];   // P [q][key]

    const int b = blockIdx.z, h = blockIdx.y, qt = blockIdx.x;
    const int tid = threadIdx.x;
    const int w = tid >> 5, lane = tid & 31;
    const int g = lane >> 2, tg = lane & 3;
    const float scale = 0.17677669529663687f;   // 1/sqrt(32)
    const unsigned full = 0xffffffffu;

    // ---- Q fragments (held in registers for whole kernel), pre-scaled ----
    const int r0 = qt * 64 + w * 16 + g;
    const int r1 = r0 + 8;
    uint32_t qa[4][4];
    {
        const float* q0p = qkv + ((size_t)(b * NQ + (r0 < NQ ? r0 : 0))) * 768 + h * HD;
        const float* q1p = qkv + ((size_t)(b * NQ + (r1 < NQ ? r1 : 0))) * 768 + h * HD;
        bool v0 = r0 < NQ, v1 = r1 < NQ;
        #pragma unroll
        for (int s = 0; s < 4; s++) {
            int c0 = s * 8 + tg, c1 = c0 + 4;
            qa[s][0] = v0 ? f2tf32(q0p[c0] * scale) : 0u;
            qa[s][1] = v1 ? f2tf32(q1p[c0] * scale) : 0u;
            qa[s][2] = v0 ? f2tf32(q0p[c1] * scale) : 0u;
            qa[s][3] = v1 ? f2tf32(q1p[c1] * scale) : 0u;
        }
    }

    float m0 = -INFINITY, m1 = -INFINITY, l0 = 0.f, l1 = 0.f;
    float O[4][4];
    #pragma unroll
    for (int nd = 0; nd < 4; nd++)
        #pragma unroll
        for (int r = 0; r < 4; r++) O[nd][r] = 0.f;

    const int NKT = (NQ + 63) / 64;   // 15
    for (int jt = 0; jt < NKT; jt++) {
        __syncthreads();
        // ---- load K tile (cvt'd) and V tile transposed (cvt'd) ----
        {
            int key = tid >> 1, dh = (tid & 1) * 16;
            int kk = jt * 64 + key;
            if (kk < NQ) {
                const float* srcK = qkv + ((size_t)(b * NQ + kk)) * 768 + 256 + h * HD + dh;
                const float* srcV = srcK + 256;
                #pragma unroll
                for (int i = 0; i < 4; i++) {
                    float4 kv = *(const float4*)(srcK + i * 4);
                    *(float4*)&Ks[key * KSTR + dh + i * 4] = make_float4(
                        __uint_as_float(f2tf32(kv.x)), __uint_as_float(f2tf32(kv.y)),
                        __uint_as_float(f2tf32(kv.z)), __uint_as_float(f2tf32(kv.w)));
                    float4 vv = *(const float4*)(srcV + i * 4);
                    Vs[(dh + i * 4 + 0) * VSTR + key] = __uint_as_float(f2tf32(vv.x));
                    Vs[(dh + i * 4 + 1) * VSTR + key] = __uint_as_float(f2tf32(vv.y));
                    Vs[(dh + i * 4 + 2) * VSTR + key] = __uint_as_float(f2tf32(vv.z));
                    Vs[(dh + i * 4 + 3) * VSTR + key] = __uint_as_float(f2tf32(vv.w));
                }
            } else {
                #pragma unroll
                for (int i = 0; i < 4; i++) {
                    *(float4*)&Ks[key * KSTR + dh + i * 4] = make_float4(0.f, 0.f, 0.f, 0.f);
                    Vs[(dh + i * 4 + 0) * VSTR + key] = 0.f;
                    Vs[(dh + i * 4 + 1) * VSTR + key] = 0.f;
                    Vs[(dh + i * 4 + 2) * VSTR + key] = 0.f;
                    Vs[(dh + i * 4 + 3) * VSTR + key] = 0.f;
                }
            }
        }
        __syncthreads();

        // ---- QK: S[16 x 64] per warp ----
        float sacc[8][4];
        #pragma unroll
        for (int ni = 0; ni < 8; ni++)
            #pragma unroll
            for (int r = 0; r < 4; r++) sacc[ni][r] = 0.f;
        #pragma unroll
        for (int s = 0; s < 4; s++) {
            #pragma unroll
            for (int ni = 0; ni < 8; ni++) {
                const float* base = &Ks[(ni * 8 + g) * KSTR + s * 8 + tg];
                uint32_t bf[2] = { __float_as_uint(base[0]), __float_as_uint(base[4]) };
                mma1688(sacc[ni], qa[s], bf);
            }
        }
        // ---- mask invalid keys ----
        int kglob = jt * 64;
        if (kglob + 64 > NQ) {
            #pragma unroll
            for (int ni = 0; ni < 8; ni++) {
                int kc = kglob + ni * 8 + 2 * tg;
                if (kc >= NQ)     { sacc[ni][0] = -1e30f; sacc[ni][2] = -1e30f; }
                if (kc + 1 >= NQ) { sacc[ni][1] = -1e30f; sacc[ni][3] = -1e30f; }
            }
        }

        // ---- online softmax (rows g and g+8; quad reduce over tg lanes) ----
        float mx0 = -INFINITY, mx1 = -INFINITY;
        #pragma unroll
        for (int ni = 0; ni < 8; ni++) {
            mx0 = fmaxf(mx0, fmaxf(sacc[ni][0], sacc[ni][1]));
            mx1 = fmaxf(mx1, fmaxf(sacc[ni][2], sacc[ni][3]));
        }
        mx0 = fmaxf(mx0, __shfl_xor_sync(full, mx0, 1));
        mx0 = fmaxf(mx0, __shfl_xor_sync(full, mx0, 2));
        mx1 = fmaxf(mx1, __shfl_xor_sync(full, mx1, 1));
        mx1 = fmaxf(mx1, __shfl_xor_sync(full, mx1, 2));
        float nm0 = fmaxf(m0, mx0), nm1 = fmaxf(m1, mx1);
        float fac0 = __expf(m0 - nm0), fac1 = __expf(m1 - nm1);
        float sum0 = 0.f, sum1 = 0.f;
        #pragma unroll
        for (int ni = 0; ni < 8; ni++) {
            sacc[ni][0] = __expf(sacc[ni][0] - nm0);
            sacc[ni][1] = __expf(sacc[ni][1] - nm0);
            sacc[ni][2] = __expf(sacc[ni][2] - nm1);
            sacc[ni][3] = __expf(sacc[ni][3] - nm1);
            sum0 += sacc[ni][0] + sacc[ni][1];
            sum1 += sacc[ni][2] + sacc[ni][3];
        }
        sum0 += __shfl_xor_sync(full, sum0, 1);
        sum0 += __shfl_xor_sync(full, sum0, 2);
        sum1 += __shfl_xor_sync(full, sum1, 1);
        sum1 += __shfl_xor_sync(full, sum1, 2);
        l0 = l0 * fac0 + sum0; m0 = nm0;
        l1 = l1 * fac1 + sum1; m1 = nm1;

        // ---- store P to smem (warp-private rows) ----
        int q0 = w * 16 + g;
        #pragma unroll
        for (int ni = 0; ni < 8; ni++) {
            *(float2*)&Ps[q0 * PSTR + ni * 8 + 2 * tg] =
                make_float2(sacc[ni][0], sacc[ni][1]);
            *(float2*)&Ps[(q0 + 8) * PSTR + ni * 8 + 2 * tg] =
                make_float2(sacc[ni][2], sacc[ni][3]);
        }
        __syncwarp();

        // ---- rescale O, then PV: O[16 x 32] += P[16 x 64] * V[64 x 32] ----
        #pragma unroll
        for (int nd = 0; nd < 4; nd++) {
            O[nd][0] *= fac0; O[nd][1] *= fac0;
            O[nd][2] *= fac1; O[nd][3] *= fac1;
        }
        #pragma unroll
        for (int s = 0; s < 8; s++) {
            const float* pb = &Ps[q0 * PSTR + s * 8 + tg];
            uint32_t pa[4] = {
                f2tf32(pb[0]), f2tf32(pb[8 * PSTR]),
                f2tf32(pb[4]), f2tf32(pb[8 * PSTR + 4]) };
            #pragma unroll
            for (int nd = 0; nd < 4; nd++) {
                const float* vb = &Vs[(nd * 8 + g) * VSTR + s * 8 + tg];
                uint32_t bf[2] = { __float_as_uint(vb[0]), __float_as_uint(vb[4]) };
                mma1688(O[nd], pa, bf);
            }
        }
    }

    // ---- epilogue ----
    float inv0 = 1.f / l0, inv1 = 1.f / l1;
    #pragma unroll
    for (int nd = 0; nd < 4; nd++) {
        int c = h * HD + nd * 8 + 2 * tg;
        if (r0 < NQ)
            *(float2*)(out + ((size_t)(b * NQ + r0)) * DD + c) =
                make_float2(O[nd][0] * inv0, O[nd][1] * inv0);
        if (r1 < NQ)
            *(float2*)(out + ((size_t)(b * NQ + r1)) * DD + c) =
                make_float2(O[nd][2] * inv1, O[nd][3] * inv1);
    }
}

// ---------------- deformable sampling: warp = (head), block = (b,q) ---------
__global__ void sample_kernel(const float* __restrict__ mem, const float* __restrict__ ref,
                              const float* __restrict__ offs, const float* __restrict__ wts,
                              float* __restrict__ fused) {
    int row = blockIdx.x;
    int b = row / NQ;
    int h = threadIdx.x >> 5;
    int lane = threadIdx.x & 31;
    const unsigned full = 0xffffffffu;
    float rx = ref[row * 2], ry = ref[row * 2 + 1];
    float gx = 0.f, gy = 0.f, wl = 0.f;
    if (lane < PP) {
        float ox = offs[(size_t)row * (HH * PP * 2) + h * (PP * 2) + lane * 2];
        float oy = offs[(size_t)row * (HH * PP * 2) + h * (PP * 2) + lane * 2 + 1];
        gx = (rx + tanhf(ox) * 0.2f) * (float)BEV - 0.5f;
        gy = (ry + tanhf(oy) * 0.2f) * (float)BEV - 0.5f;
        wl = wts[(size_t)row * (HH * PP) + h * PP + lane];
    }
    float m = wl;
    m = fmaxf(m, __shfl_xor_sync(full, m, 1));
    m = fmaxf(m, __shfl_xor_sync(full, m, 2));
    float e = __expf(wl - m);
    float ssum = e;
    ssum += __shfl_xor_sync(full, ssum, 1);
    ssum += __shfl_xor_sync(full, ssum, 2);
    float w = e / ssum;
    const float* mb = mem + (size_t)b * (BEV * BEV) * DD + h * HD + lane;
    float acc = 0.f;
    #pragma unroll
    for (int p = 0; p < PP; p++) {
        float px = __shfl_sync(full, gx, p);
        float py = __shfl_sync(full, gy, p);
        float pw = __shfl_sync(full, w, p);
        float x0f = floorf(px), y0f = floorf(py);
        float wx1 = px - x0f, wy1 = py - y0f;
        float wx0 = 1.f - wx1, wy0 = 1.f - wy1;
        int x0 = (int)x0f, y0 = (int)y0f;
        bool xv0 = (x0 >= 0) && (x0 < BEV);
        bool xv1 = (x0 + 1 >= 0) && (x0 + 1 < BEV);
        bool yv0 = (y0 >= 0) && (y0 < BEV);
        bool yv1 = (y0 + 1 >= 0) && (y0 + 1 < BEV);
        float v = 0.f;
        if (yv0) {
            if (xv0) v += wx0 * wy0 * mb[(size_t)(y0 * BEV + x0) * DD];
            if (xv1) v += wx1 * wy0 * mb[(size_t)(y0 * BEV + x0 + 1) * DD];
        }
        if (yv1) {
            if (xv0) v += wx0 * wy1 * mb[(size_t)((y0 + 1) * BEV + x0) * DD];
            if (xv1) v += wx1 * wy1 * mb[(size_t)((y0 + 1) * BEV + x0 + 1) * DD];
        }
        acc += pw * v;
    }
    fused[(size_t)row * DD + h * HD + lane] = acc;
}

// ---------------- host launcher ---------------------------------------------
extern "C" void kernel_launch(void* const* d_in, const int* in_sizes, int n_in,
                              void* d_out, int out_size) {
    const float* query = (const float*)d_in[0];
    const float* memory = (const float*)d_in[1];
    const float* refp  = (const float*)d_in[2];
    const float* qpos  = (const float*)d_in[3];
    const float* in_w  = (const float*)d_in[4];
    const float* in_b  = (const float*)d_in[5];
    const float* out_w = (const float*)d_in[6];
    const float* out_b = (const float*)d_in[7];
    const float* off_w = (const float*)d_in[8];
    const float* off_b = (const float*)d_in[9];
    const float* wt_w  = (const float*)d_in[10];
    const float* wt_b  = (const float*)d_in[11];
    const float* co_w  = (const float*)d_in[12];
    const float* co_b  = (const float*)d_in[13];
    const float* f_w1  = (const float*)d_in[14];
    const float* f_b1  = (const float*)d_in[15];
    const float* f_w2  = (const float*)d_in[16];
    const float* f_b2  = (const float*)d_in[17];
    const float* n1s   = (const float*)d_in[18];
    const float* n1b   = (const float*)d_in[19];
    const float* n2s   = (const float*)d_in[20];
    const float* n2b   = (const float*)d_in[21];
    const float* n3s   = (const float*)d_in[22];
    const float* n3b   = (const float*)d_in[23];

    float *qin, *qkv, *attn, *q1, *q2, *offs, *wts, *fused, *qq2, *q3, *mid;
    cudaGetSymbolAddress((void**)&qin,   g_qin);
    cudaGetSymbolAddress((void**)&qkv,   g_qkv);
    cudaGetSymbolAddress((void**)&attn,  g_attn);
    cudaGetSymbolAddress((void**)&q1,    g_q1);
    cudaGetSymbolAddress((void**)&q2,    g_q2);
    cudaGetSymbolAddress((void**)&offs,  g_offs);
    cudaGetSymbolAddress((void**)&wts,   g_wts);
    cudaGetSymbolAddress((void**)&fused, g_fused);
    cudaGetSymbolAddress((void**)&qq2,   g_qq2);
    cudaGetSymbolAddress((void**)&q3,    g_q3);
    cudaGetSymbolAddress((void**)&mid,   g_mid);

    const int M = MROWS;
    const int MTC = (M + 127) / 128;     // 57
    const int MT64 = (M + 63) / 64;      // 113

    // 1. q_in = LN(query + query_pos)
    add_ln_kernel<<<M, 256>>>(query, qpos, n1s, n1b, qin);
    // 2. qkv = q_in @ in_w^T + in_b
    gemm_tc<<<dim3(12, MTC), 256>>>(qin, in_w, in_b, nullptr, qkv, M, 768, 256, 0);
    // 3. self-attention (tensor-core flash)
    attn3_kernel<<<dim3((NQ + 63) / 64, HH, BB), 128>>>(qkv, attn);
    // 4. q1 = attn @ out_w^T + out_b + query
    gemm_tc<<<dim3(4, MTC), 256>>>(attn, out_w, out_b, query, q1, M, 256, 256, 0);
    // 5. q2 = LN(q1 + query_pos)
    add_ln_kernel<<<M, 256>>>(q1, qpos, n2s, n2b, q2);
    // 6/7. offset + weight heads
    gemm_tc<<<dim3(1, MTC), 256>>>(q2, off_w, off_b, nullptr, offs, M, 64, 256, 0);
    gemm_nt<<<dim3(1, MT64), 256>>>(q2, wt_w, wt_b, nullptr, wts, M, 32, 256, 0);
    // 8. deformable BEV sampling -> fused
    sample_kernel<<<M, 256>>>(memory, refp, offs, wts, fused);
    // 9. qq2 = fused @ co_w^T + co_b + q1
    gemm_tc<<<dim3(4, MTC), 256>>>(fused, co_w, co_b, q1, qq2, M, 256, 256, 0);
    // 10. q3 = LN(qq2)
    add_ln_kernel<<<M, 256>>>(qq2, nullptr, n3s, n3b, q3);
    // 11. mid = relu(q3 @ f_w1^T + f_b1)
    gemm_tc<<<dim3(8, MTC), 256>>>(q3, f_w1, f_b1, nullptr, mid, M, 512, 256, 1);
    // 12. out = mid @ f_w2^T + f_b2 + qq2
    gemm_tc<<<dim3(4, MTC), 256>>>(mid, f_w2, f_b2, qq2, (float*)d_out, M, 256, 512, 0);
    (void)in_sizes; (void)n_in; (void)out_size;
}